// round 1
// baseline (speedup 1.0000x reference)
#include <cuda_runtime.h>

#define BB   2
#define TT   2048
#define KK   1024
#define HH   16
#define SS   64
#define MROWS (BB*TT)   // 4096

// ---- scratch (static device globals; no allocation allowed) ----
__device__ float g_Q [BB*TT*KK];
__device__ float g_K [BB*TT*KK];
__device__ float g_V [BB*TT*KK];
__device__ float g_ys[BB*TT*KK];

// ============================================================================
// GEMM: C[M,N] = A[M,Kd] @ B[N,Kd]^T (+ bias)   (both operands K-major)
// BM=BN=64, BK=16, 256 threads, 4x4 microtile per thread.
// ============================================================================
#define BM 64
#define BN 64
#define BK 16

__global__ __launch_bounds__(256)
void gemm_abt_kernel(const float* __restrict__ A,
                     const float* __restrict__ B,
                     const float* __restrict__ bias,
                     float* __restrict__ C,
                     int M, int N, int Kd)
{
    __shared__ float As[BK][BM];
    __shared__ float Bs[BK][BN];

    const int tid = threadIdx.x;
    const int tx  = tid & 15;       // 0..15 -> N microtile
    const int ty  = tid >> 4;       // 0..15 -> M microtile
    const int m0  = blockIdx.y * BM;
    const int n0  = blockIdx.x * BN;

    // loader mapping: 256 threads cover 64 rows x 4 float4 (=16 floats)
    const int lr = tid >> 2;        // 0..63 row in tile
    const int lc = tid & 3;         // 0..3  float4 column in BK
    const float* Ap = A + (size_t)(m0 + lr) * Kd + lc * 4;
    const float* Bp = B + (size_t)(n0 + lr) * Kd + lc * 4;

    float acc[4][4];
#pragma unroll
    for (int i = 0; i < 4; i++)
#pragma unroll
        for (int j = 0; j < 4; j++) acc[i][j] = 0.f;

    for (int k0 = 0; k0 < Kd; k0 += BK) {
        float4 a4 = *(const float4*)(Ap + k0);
        float4 b4 = *(const float4*)(Bp + k0);
        __syncthreads();
        As[lc*4+0][lr] = a4.x; As[lc*4+1][lr] = a4.y;
        As[lc*4+2][lr] = a4.z; As[lc*4+3][lr] = a4.w;
        Bs[lc*4+0][lr] = b4.x; Bs[lc*4+1][lr] = b4.y;
        Bs[lc*4+2][lr] = b4.z; Bs[lc*4+3][lr] = b4.w;
        __syncthreads();
#pragma unroll
        for (int kk = 0; kk < BK; kk++) {
            float4 af = *(const float4*)&As[kk][ty*4];
            float4 bf = *(const float4*)&Bs[kk][tx*4];
            float a[4] = {af.x, af.y, af.z, af.w};
            float b[4] = {bf.x, bf.y, bf.z, bf.w};
#pragma unroll
            for (int i = 0; i < 4; i++)
#pragma unroll
                for (int j = 0; j < 4; j++)
                    acc[i][j] += a[i] * b[j];
        }
    }

    float bv[4] = {0.f, 0.f, 0.f, 0.f};
    if (bias) {
#pragma unroll
        for (int j = 0; j < 4; j++) bv[j] = bias[n0 + tx*4 + j];
    }
#pragma unroll
    for (int i = 0; i < 4; i++) {
        float4 o;
        o.x = acc[i][0] + bv[0];
        o.y = acc[i][1] + bv[1];
        o.z = acc[i][2] + bv[2];
        o.w = acc[i][3] + bv[3];
        *(float4*)&C[(size_t)(m0 + ty*4 + i) * N + n0 + tx*4] = o;
    }
}

// ============================================================================
// Flash-style attention, fp32. One CTA = 64 queries of one (b, h).
// q row + accumulator in registers; K/V 64x64 tiles in smem; streaming
// online softmax; masked keys (mask==0) skipped entirely.
// ============================================================================
__global__ __launch_bounds__(64)
void attn_kernel(const float* __restrict__ Q,
                 const float* __restrict__ Kb,
                 const float* __restrict__ V,
                 const int*   __restrict__ mask,
                 float* __restrict__ ys)
{
    __shared__ float ks[64][64];
    __shared__ float vs[64][64];
    __shared__ int   msk[64];

    const int t = threadIdx.x;           // 0..63, one query row per thread
    const int h = blockIdx.y;
    const int b = blockIdx.z;
    const int q = blockIdx.x * 64 + t;

    const float* qptr = Q + ((size_t)(b*TT + q)) * KK + h * SS;
    float qr[64];
#pragma unroll
    for (int c = 0; c < 16; c++) {
        float4 v4 = *(const float4*)(qptr + 4*c);
        qr[4*c+0] = v4.x; qr[4*c+1] = v4.y; qr[4*c+2] = v4.z; qr[4*c+3] = v4.w;
    }

    float m = -1e30f, l = 0.f;
    float acc[64];
#pragma unroll
    for (int d = 0; d < 64; d++) acc[d] = 0.f;

    const float* Kbase = Kb + ((size_t)b*TT) * KK + h * SS;
    const float* Vbase = V  + ((size_t)b*TT) * KK + h * SS;
    const int*   mbase = mask + b*TT;

    for (int n0 = 0; n0 < TT; n0 += 64) {
        __syncthreads();
        // cooperative coalesced load of K/V tiles (64 rows x 64 floats)
#pragma unroll
        for (int i = 0; i < 16; i++) {
            int f   = i*64 + t;          // float4 index within tile
            int row = f >> 4;
            int c4  = f & 15;
            const float* kp = Kbase + (size_t)(n0 + row) * KK + c4*4;
            const float* vp = Vbase + (size_t)(n0 + row) * KK + c4*4;
            *(float4*)&ks[row][c4*4] = *(const float4*)kp;
            *(float4*)&vs[row][c4*4] = *(const float4*)vp;
        }
        msk[t] = mbase[n0 + t];
        __syncthreads();

#pragma unroll 1
        for (int j = 0; j < 64; j++) {
            if (msk[j] == 0) continue;
            float s0 = 0.f, s1 = 0.f, s2 = 0.f, s3 = 0.f;
#pragma unroll
            for (int c = 0; c < 16; c++) {
                float4 kf = *(const float4*)&ks[j][c*4];
                s0 += qr[4*c+0] * kf.x;
                s1 += qr[4*c+1] * kf.y;
                s2 += qr[4*c+2] * kf.z;
                s3 += qr[4*c+3] * kf.w;
            }
            float s = (s0 + s1) + (s2 + s3);
            if (s > m) {                 // rare: rescale running state
                float r = __expf(m - s);
                l *= r;
#pragma unroll
                for (int d = 0; d < 64; d++) acc[d] *= r;
                m = s;
            }
            float p = __expf(s - m);
            l += p;
#pragma unroll
            for (int c = 0; c < 16; c++) {
                float4 vf = *(const float4*)&vs[j][c*4];
                acc[4*c+0] += p * vf.x;
                acc[4*c+1] += p * vf.y;
                acc[4*c+2] += p * vf.z;
                acc[4*c+3] += p * vf.w;
            }
        }
    }

    float inv = 1.f / l;
    float* op = ys + ((size_t)(b*TT + q)) * KK + h * SS;
#pragma unroll
    for (int c = 0; c < 16; c++) {
        float4 o;
        o.x = acc[4*c+0] * inv;
        o.y = acc[4*c+1] * inv;
        o.z = acc[4*c+2] * inv;
        o.w = acc[4*c+3] * inv;
        *(float4*)(op + 4*c) = o;
    }
}

// ============================================================================
// launch
// ============================================================================
extern "C" void kernel_launch(void* const* d_in, const int* in_sizes, int n_in,
                              void* d_out, int out_size)
{
    const float* x    = (const float*)d_in[0];
    const int*   mask = (const int*)  d_in[1];
    const float* Wk   = (const float*)d_in[2];
    const float* Wq   = (const float*)d_in[3];
    const float* Wv   = (const float*)d_in[4];
    const float* Wu   = (const float*)d_in[5];
    const float* bu   = (const float*)d_in[6];
    float* out = (float*)d_out;

    float *Q, *Kb, *V, *ys;
    cudaGetSymbolAddress((void**)&Q,  g_Q);
    cudaGetSymbolAddress((void**)&Kb, g_K);
    cudaGetSymbolAddress((void**)&V,  g_V);
    cudaGetSymbolAddress((void**)&ys, g_ys);

    dim3 gg(KK / BN, MROWS / BM);   // (16, 64)
    gemm_abt_kernel<<<gg, 256>>>(x, Wq, nullptr, Q,  MROWS, KK, KK);
    gemm_abt_kernel<<<gg, 256>>>(x, Wk, nullptr, Kb, MROWS, KK, KK);
    gemm_abt_kernel<<<gg, 256>>>(x, Wv, nullptr, V,  MROWS, KK, KK);

    dim3 ga(TT / 64, HH, BB);       // (32, 16, 2)
    attn_kernel<<<ga, 64>>>(Q, Kb, V, mask, ys);

    gemm_abt_kernel<<<gg, 256>>>(ys, Wu, bu, out, MROWS, KK, KK);
}

// round 4
// speedup vs baseline: 1.5579x; 1.5579x over previous
#include <cuda_runtime.h>
#include <cuda_bf16.h>
#include <cstdint>

#define BB   2
#define TT   2048
#define KK   1024
#define HH   16
#define SS   64
#define MROWS (BB*TT)   // 4096

// ---- scratch (static device globals; no allocation allowed) ----
__device__ float g_Q [BB*TT*KK];
__device__ float g_K [BB*TT*KK];
__device__ float g_V [BB*TT*KK];
__device__ float g_ys[BB*TT*KK];

// ============================================================================
// Split-bf16 (bf16x3) tensor-core GEMM via mma.sync.m16n8k16.
// C[M,N] = A[M,1024] @ B[N,1024]^T (+ bias), fp32 in/out.
// x = hi + lo (both bf16);  A.B ~= Ahi.Bhi + Ahi.Blo + Alo.Bhi  (fp32 accum).
// CTA tile 128x128, BK=32 double-buffered, 8 warps (2m x 4n), warp tile 64x32.
// ============================================================================
#define GBM 128
#define GBN 128
#define GBK 32
#define NIT (KK / GBK)            // 32
#define BKP 40                    // padded bf16 row stride
#define TILE (128 * BKP)          // bf16 elems per tile buffer (5120)
// 8 tiles: Ahi[2], Alo[2], Bhi[2], Blo[2]
#define GEMM_SMEM (8 * TILE * 2)  // 81920 bytes

__device__ __forceinline__ void mma_bf16(float d[4],
                                         uint32_t a0, uint32_t a1, uint32_t a2, uint32_t a3,
                                         uint32_t b0, uint32_t b1) {
    asm volatile(
        "mma.sync.aligned.m16n8k16.row.col.f32.bf16.bf16.f32 "
        "{%0,%1,%2,%3}, {%4,%5,%6,%7}, {%8,%9}, {%0,%1,%2,%3};"
        : "+f"(d[0]), "+f"(d[1]), "+f"(d[2]), "+f"(d[3])
        : "r"(a0), "r"(a1), "r"(a2), "r"(a3), "r"(b0), "r"(b1));
}

__device__ __forceinline__ void split_bf16(float x, __nv_bfloat16& h, __nv_bfloat16& l) {
    h = __float2bfloat16(x);
    l = __float2bfloat16(x - __bfloat162float(h));
}

__global__ __launch_bounds__(256)
void gemm_mma_kernel(const float* __restrict__ A,
                     const float* __restrict__ B,
                     const float* __restrict__ bias,
                     float* __restrict__ C,
                     int M, int N)
{
    extern __shared__ __nv_bfloat16 sm[];
    __nv_bfloat16* Ahi = sm;
    __nv_bfloat16* Alo = sm + 2 * TILE;
    __nv_bfloat16* Bhi = sm + 4 * TILE;
    __nv_bfloat16* Blo = sm + 6 * TILE;

    const int tid  = threadIdx.x;
    const int lane = tid & 31;
    const int wid  = tid >> 5;
    const int g    = lane >> 2;      // 0..7
    const int tg   = lane & 3;       // 0..3
    const int wm   = wid & 1;        // 0..1
    const int wn   = wid >> 1;       // 0..3
    const int m0   = blockIdx.y * GBM;
    const int n0   = blockIdx.x * GBN;

    const float* Ag = A + (size_t)m0 * KK;
    const float* Bg = B + (size_t)n0 * KK;

    float acc[4][4][4];
#pragma unroll
    for (int i = 0; i < 4; i++)
#pragma unroll
        for (int j = 0; j < 4; j++)
#pragma unroll
            for (int r = 0; r < 4; r++) acc[i][j][r] = 0.f;

    float4 ra[4], rb[4];

    // loader mapping: idx = j*256+tid; row = idx>>3 (0..127), c4 = idx&7 (0..7)
#define LOAD_TILES(k0) do { \
    _Pragma("unroll") \
    for (int j = 0; j < 4; j++) { \
        int idx = j * 256 + tid; int row = idx >> 3; int c4 = idx & 7; \
        ra[j] = *(const float4*)(Ag + (size_t)row * KK + (k0) + c4 * 4); \
        rb[j] = *(const float4*)(Bg + (size_t)row * KK + (k0) + c4 * 4); \
    } } while (0)

#define STORE_TILES(bsel) do { \
    _Pragma("unroll") \
    for (int j = 0; j < 4; j++) { \
        int idx = j * 256 + tid; int row = idx >> 3; int c4 = idx & 7; \
        int off = (bsel) * TILE + row * BKP + c4 * 4; \
        __nv_bfloat16 h0,l0,h1,l1,h2,l2,h3,l3; \
        split_bf16(ra[j].x, h0, l0); split_bf16(ra[j].y, h1, l1); \
        split_bf16(ra[j].z, h2, l2); split_bf16(ra[j].w, h3, l3); \
        *(__nv_bfloat162*)&Ahi[off]     = __nv_bfloat162(h0, h1); \
        *(__nv_bfloat162*)&Ahi[off + 2] = __nv_bfloat162(h2, h3); \
        *(__nv_bfloat162*)&Alo[off]     = __nv_bfloat162(l0, l1); \
        *(__nv_bfloat162*)&Alo[off + 2] = __nv_bfloat162(l2, l3); \
        split_bf16(rb[j].x, h0, l0); split_bf16(rb[j].y, h1, l1); \
        split_bf16(rb[j].z, h2, l2); split_bf16(rb[j].w, h3, l3); \
        *(__nv_bfloat162*)&Bhi[off]     = __nv_bfloat162(h0, h1); \
        *(__nv_bfloat162*)&Bhi[off + 2] = __nv_bfloat162(h2, h3); \
        *(__nv_bfloat162*)&Blo[off]     = __nv_bfloat162(l0, l1); \
        *(__nv_bfloat162*)&Blo[off + 2] = __nv_bfloat162(l2, l3); \
    } } while (0)

    LOAD_TILES(0);
    STORE_TILES(0);
    __syncthreads();

    const int arow = (wm * 64 + g) * BKP;   // bf16-unit offset of this warp's A rows
    const int brow = (wn * 32 + g) * BKP;

    for (int it = 0; it < NIT; it++) {
        const int buf = it & 1;
        if (it + 1 < NIT) LOAD_TILES((it + 1) * GBK);

        const __nv_bfloat16* pah = Ahi + buf * TILE + arow;
        const __nv_bfloat16* pal = Alo + buf * TILE + arow;
        const __nv_bfloat16* pbh = Bhi + buf * TILE + brow;
        const __nv_bfloat16* pbl = Blo + buf * TILE + brow;

#pragma unroll
        for (int ks = 0; ks < 2; ks++) {
            const int kk = ks * 16 + 2 * tg;
            uint32_t bh[4][2], bl[4][2];
#pragma unroll
            for (int nf = 0; nf < 4; nf++) {
                bh[nf][0] = *(const uint32_t*)&pbh[nf * 8 * BKP + kk];
                bh[nf][1] = *(const uint32_t*)&pbh[nf * 8 * BKP + kk + 8];
                bl[nf][0] = *(const uint32_t*)&pbl[nf * 8 * BKP + kk];
                bl[nf][1] = *(const uint32_t*)&pbl[nf * 8 * BKP + kk + 8];
            }
#pragma unroll
            for (int mf = 0; mf < 4; mf++) {
                const int r0 = mf * 16 * BKP;
                const int r8 = r0 + 8 * BKP;
                uint32_t ah0 = *(const uint32_t*)&pah[r0 + kk];
                uint32_t ah1 = *(const uint32_t*)&pah[r8 + kk];
                uint32_t ah2 = *(const uint32_t*)&pah[r0 + kk + 8];
                uint32_t ah3 = *(const uint32_t*)&pah[r8 + kk + 8];
                uint32_t al0 = *(const uint32_t*)&pal[r0 + kk];
                uint32_t al1 = *(const uint32_t*)&pal[r8 + kk];
                uint32_t al2 = *(const uint32_t*)&pal[r0 + kk + 8];
                uint32_t al3 = *(const uint32_t*)&pal[r8 + kk + 8];
#pragma unroll
                for (int nf = 0; nf < 4; nf++) {
                    mma_bf16(acc[mf][nf], ah0, ah1, ah2, ah3, bh[nf][0], bh[nf][1]);
                    mma_bf16(acc[mf][nf], ah0, ah1, ah2, ah3, bl[nf][0], bl[nf][1]);
                    mma_bf16(acc[mf][nf], al0, al1, al2, al3, bh[nf][0], bh[nf][1]);
                }
            }
        }

        if (it + 1 < NIT) {
            __syncthreads();
            STORE_TILES(buf ^ 1);
            __syncthreads();
        }
    }

    // epilogue
#pragma unroll
    for (int mf = 0; mf < 4; mf++) {
        int r0 = m0 + wm * 64 + mf * 16 + g;
#pragma unroll
        for (int nf = 0; nf < 4; nf++) {
            int col = n0 + wn * 32 + nf * 8 + tg * 2;
            float b0 = 0.f, b1 = 0.f;
            if (bias) { b0 = __ldg(&bias[col]); b1 = __ldg(&bias[col + 1]); }
            float2 o0 = { acc[mf][nf][0] + b0, acc[mf][nf][1] + b1 };
            float2 o1 = { acc[mf][nf][2] + b0, acc[mf][nf][3] + b1 };
            *(float2*)&C[(size_t)r0 * N + col]       = o0;
            *(float2*)&C[(size_t)(r0 + 8) * N + col] = o1;
        }
    }
#undef LOAD_TILES
#undef STORE_TILES
}

// ============================================================================
// Flash-style attention, fp32 (unchanged).
// ============================================================================
__global__ __launch_bounds__(64)
void attn_kernel(const float* __restrict__ Q,
                 const float* __restrict__ Kb,
                 const float* __restrict__ V,
                 const int*   __restrict__ mask,
                 float* __restrict__ ys)
{
    __shared__ float ks[64][64];
    __shared__ float vs[64][64];
    __shared__ int   msk[64];

    const int t = threadIdx.x;
    const int h = blockIdx.y;
    const int b = blockIdx.z;
    const int q = blockIdx.x * 64 + t;

    const float* qptr = Q + ((size_t)(b*TT + q)) * KK + h * SS;
    float qr[64];
#pragma unroll
    for (int c = 0; c < 16; c++) {
        float4 v4 = *(const float4*)(qptr + 4*c);
        qr[4*c+0] = v4.x; qr[4*c+1] = v4.y; qr[4*c+2] = v4.z; qr[4*c+3] = v4.w;
    }

    float m = -1e30f, l = 0.f;
    float acc[64];
#pragma unroll
    for (int d = 0; d < 64; d++) acc[d] = 0.f;

    const float* Kbase = Kb + ((size_t)b*TT) * KK + h * SS;
    const float* Vbase = V  + ((size_t)b*TT) * KK + h * SS;
    const int*   mbase = mask + b*TT;

    for (int n0 = 0; n0 < TT; n0 += 64) {
        __syncthreads();
#pragma unroll
        for (int i = 0; i < 16; i++) {
            int f   = i*64 + t;
            int row = f >> 4;
            int c4  = f & 15;
            const float* kp = Kbase + (size_t)(n0 + row) * KK + c4*4;
            const float* vp = Vbase + (size_t)(n0 + row) * KK + c4*4;
            *(float4*)&ks[row][c4*4] = *(const float4*)kp;
            *(float4*)&vs[row][c4*4] = *(const float4*)vp;
        }
        msk[t] = mbase[n0 + t];
        __syncthreads();

#pragma unroll 1
        for (int j = 0; j < 64; j++) {
            if (msk[j] == 0) continue;
            float s0 = 0.f, s1 = 0.f, s2 = 0.f, s3 = 0.f;
#pragma unroll
            for (int c = 0; c < 16; c++) {
                float4 kf = *(const float4*)&ks[j][c*4];
                s0 += qr[4*c+0] * kf.x;
                s1 += qr[4*c+1] * kf.y;
                s2 += qr[4*c+2] * kf.z;
                s3 += qr[4*c+3] * kf.w;
            }
            float s = (s0 + s1) + (s2 + s3);
            if (s > m) {
                float r = __expf(m - s);
                l *= r;
#pragma unroll
                for (int d = 0; d < 64; d++) acc[d] *= r;
                m = s;
            }
            float p = __expf(s - m);
            l += p;
#pragma unroll
            for (int c = 0; c < 16; c++) {
                float4 vf = *(const float4*)&vs[j][c*4];
                acc[4*c+0] += p * vf.x;
                acc[4*c+1] += p * vf.y;
                acc[4*c+2] += p * vf.z;
                acc[4*c+3] += p * vf.w;
            }
        }
    }

    float inv = 1.f / l;
    float* op = ys + ((size_t)(b*TT + q)) * KK + h * SS;
#pragma unroll
    for (int c = 0; c < 16; c++) {
        float4 o;
        o.x = acc[4*c+0] * inv;
        o.y = acc[4*c+1] * inv;
        o.z = acc[4*c+2] * inv;
        o.w = acc[4*c+3] * inv;
        *(float4*)(op + 4*c) = o;
    }
}

// ============================================================================
// launch
// ============================================================================
extern "C" void kernel_launch(void* const* d_in, const int* in_sizes, int n_in,
                              void* d_out, int out_size)
{
    const float* x    = (const float*)d_in[0];
    const int*   mask = (const int*)  d_in[1];
    const float* Wk   = (const float*)d_in[2];
    const float* Wq   = (const float*)d_in[3];
    const float* Wv   = (const float*)d_in[4];
    const float* Wu   = (const float*)d_in[5];
    const float* bu   = (const float*)d_in[6];
    float* out = (float*)d_out;

    float *Q, *Kb, *V, *ys;
    cudaGetSymbolAddress((void**)&Q,  g_Q);
    cudaGetSymbolAddress((void**)&Kb, g_K);
    cudaGetSymbolAddress((void**)&V,  g_V);
    cudaGetSymbolAddress((void**)&ys, g_ys);

    cudaFuncSetAttribute(gemm_mma_kernel,
                         cudaFuncAttributeMaxDynamicSharedMemorySize, GEMM_SMEM);

    dim3 gg(KK / GBN, MROWS / GBM);   // (8, 32)
    gemm_mma_kernel<<<gg, 256, GEMM_SMEM>>>(x, Wq, nullptr, Q,  MROWS, KK);
    gemm_mma_kernel<<<gg, 256, GEMM_SMEM>>>(x, Wk, nullptr, Kb, MROWS, KK);
    gemm_mma_kernel<<<gg, 256, GEMM_SMEM>>>(x, Wv, nullptr, V,  MROWS, KK);

    dim3 ga(TT / 64, HH, BB);         // (32, 16, 2)
    attn_kernel<<<ga, 64>>>(Q, Kb, V, mask, ys);

    gemm_mma_kernel<<<gg, 256, GEMM_SMEM>>>(ys, Wu, bu, out, MROWS, KK);
}

// round 5
// speedup vs baseline: 3.0886x; 1.9825x over previous
#include <cuda_runtime.h>
#include <cuda_bf16.h>
#include <cstdint>

#define BB   2
#define TT   2048
#define KK   1024
#define HH   16
#define SS   64
#define MROWS (BB*TT)   // 4096

// ---- scratch (static device globals; no allocation allowed) ----
__device__ float g_Q [BB*TT*KK];
__device__ float g_K [BB*TT*KK];
__device__ float g_V [BB*TT*KK];
__device__ float g_ys[BB*TT*KK];
__device__ int   g_idx[BB*TT];
__device__ int   g_nv [BB];

// ============================================================================
// common helpers
// ============================================================================
__device__ __forceinline__ void mma_bf16(float d[4],
                                         uint32_t a0, uint32_t a1, uint32_t a2, uint32_t a3,
                                         uint32_t b0, uint32_t b1) {
    asm volatile(
        "mma.sync.aligned.m16n8k16.row.col.f32.bf16.bf16.f32 "
        "{%0,%1,%2,%3}, {%4,%5,%6,%7}, {%8,%9}, {%0,%1,%2,%3};"
        : "+f"(d[0]), "+f"(d[1]), "+f"(d[2]), "+f"(d[3])
        : "r"(a0), "r"(a1), "r"(a2), "r"(a3), "r"(b0), "r"(b1));
}

__device__ __forceinline__ void split_bf16(float x, __nv_bfloat16& h, __nv_bfloat16& l) {
    h = __float2bfloat16(x);
    l = __float2bfloat16(x - __bfloat162float(h));
}

// split a float2 into packed bf16x2 hi / lo registers
__device__ __forceinline__ void split2(float2 f, uint32_t& h, uint32_t& l) {
    __nv_bfloat162 hh = __float22bfloat162_rn(f);
    float2 hf = __bfloat1622float2(hh);
    __nv_bfloat162 ll = __float22bfloat162_rn(make_float2(f.x - hf.x, f.y - hf.y));
    h = *(uint32_t*)&hh;
    l = *(uint32_t*)&ll;
}

// ============================================================================
// mask compaction: deterministic block scan, one CTA per batch.
// idx[b][0..nv-1] = ascending t with mask==1; g_nv[b] = count.
// ============================================================================
__global__ __launch_bounds__(1024)
void compact_kernel(const int* __restrict__ mask, int* __restrict__ idx,
                    int* __restrict__ nv)
{
    __shared__ int s[1024];
    const int b = blockIdx.x;
    const int t = threadIdx.x;
    const int m0 = mask[b * TT + 2 * t];
    const int m1 = mask[b * TT + 2 * t + 1];
    const int c  = m0 + m1;
    s[t] = c;
    __syncthreads();
    for (int off = 1; off < 1024; off <<= 1) {
        int v = s[t];
        int u = (t >= off) ? s[t - off] : 0;
        __syncthreads();
        s[t] = v + u;
        __syncthreads();
    }
    const int incl = s[t];
    const int excl = incl - c;
    if (m0) idx[b * TT + excl] = 2 * t;
    if (m1) idx[b * TT + excl + m0] = 2 * t + 1;
    if (t == 1023) nv[b] = incl;
}

// ============================================================================
// Split-bf16 tensor-core GEMM (unchanged, proven): C = A @ B^T (+ bias)
// ============================================================================
#define GBM 128
#define GBN 128
#define GBK 32
#define NIT (KK / GBK)
#define BKP 40
#define TILE (128 * BKP)
#define GEMM_SMEM (8 * TILE * 2)

__global__ __launch_bounds__(256)
void gemm_mma_kernel(const float* __restrict__ A,
                     const float* __restrict__ B,
                     const float* __restrict__ bias,
                     float* __restrict__ C,
                     int M, int N)
{
    extern __shared__ __nv_bfloat16 sm[];
    __nv_bfloat16* Ahi = sm;
    __nv_bfloat16* Alo = sm + 2 * TILE;
    __nv_bfloat16* Bhi = sm + 4 * TILE;
    __nv_bfloat16* Blo = sm + 6 * TILE;

    const int tid  = threadIdx.x;
    const int lane = tid & 31;
    const int wid  = tid >> 5;
    const int g    = lane >> 2;
    const int tg   = lane & 3;
    const int wm   = wid & 1;
    const int wn   = wid >> 1;
    const int m0   = blockIdx.y * GBM;
    const int n0   = blockIdx.x * GBN;

    const float* Ag = A + (size_t)m0 * KK;
    const float* Bg = B + (size_t)n0 * KK;

    float acc[4][4][4];
#pragma unroll
    for (int i = 0; i < 4; i++)
#pragma unroll
        for (int j = 0; j < 4; j++)
#pragma unroll
            for (int r = 0; r < 4; r++) acc[i][j][r] = 0.f;

    float4 ra[4], rb[4];

#define LOAD_TILES(k0) do { \
    _Pragma("unroll") \
    for (int j = 0; j < 4; j++) { \
        int idx = j * 256 + tid; int row = idx >> 3; int c4 = idx & 7; \
        ra[j] = *(const float4*)(Ag + (size_t)row * KK + (k0) + c4 * 4); \
        rb[j] = *(const float4*)(Bg + (size_t)row * KK + (k0) + c4 * 4); \
    } } while (0)

#define STORE_TILES(bsel) do { \
    _Pragma("unroll") \
    for (int j = 0; j < 4; j++) { \
        int idx = j * 256 + tid; int row = idx >> 3; int c4 = idx & 7; \
        int off = (bsel) * TILE + row * BKP + c4 * 4; \
        __nv_bfloat16 h0,l0,h1,l1,h2,l2,h3,l3; \
        split_bf16(ra[j].x, h0, l0); split_bf16(ra[j].y, h1, l1); \
        split_bf16(ra[j].z, h2, l2); split_bf16(ra[j].w, h3, l3); \
        *(__nv_bfloat162*)&Ahi[off]     = __nv_bfloat162(h0, h1); \
        *(__nv_bfloat162*)&Ahi[off + 2] = __nv_bfloat162(h2, h3); \
        *(__nv_bfloat162*)&Alo[off]     = __nv_bfloat162(l0, l1); \
        *(__nv_bfloat162*)&Alo[off + 2] = __nv_bfloat162(l2, l3); \
        split_bf16(rb[j].x, h0, l0); split_bf16(rb[j].y, h1, l1); \
        split_bf16(rb[j].z, h2, l2); split_bf16(rb[j].w, h3, l3); \
        *(__nv_bfloat162*)&Bhi[off]     = __nv_bfloat162(h0, h1); \
        *(__nv_bfloat162*)&Bhi[off + 2] = __nv_bfloat162(h2, h3); \
        *(__nv_bfloat162*)&Blo[off]     = __nv_bfloat162(l0, l1); \
        *(__nv_bfloat162*)&Blo[off + 2] = __nv_bfloat162(l2, l3); \
    } } while (0)

    LOAD_TILES(0);
    STORE_TILES(0);
    __syncthreads();

    const int arow = (wm * 64 + g) * BKP;
    const int brow = (wn * 32 + g) * BKP;

    for (int it = 0; it < NIT; it++) {
        const int buf = it & 1;
        if (it + 1 < NIT) LOAD_TILES((it + 1) * GBK);

        const __nv_bfloat16* pah = Ahi + buf * TILE + arow;
        const __nv_bfloat16* pal = Alo + buf * TILE + arow;
        const __nv_bfloat16* pbh = Bhi + buf * TILE + brow;
        const __nv_bfloat16* pbl = Blo + buf * TILE + brow;

#pragma unroll
        for (int ks = 0; ks < 2; ks++) {
            const int kk = ks * 16 + 2 * tg;
            uint32_t bh[4][2], bl[4][2];
#pragma unroll
            for (int nf = 0; nf < 4; nf++) {
                bh[nf][0] = *(const uint32_t*)&pbh[nf * 8 * BKP + kk];
                bh[nf][1] = *(const uint32_t*)&pbh[nf * 8 * BKP + kk + 8];
                bl[nf][0] = *(const uint32_t*)&pbl[nf * 8 * BKP + kk];
                bl[nf][1] = *(const uint32_t*)&pbl[nf * 8 * BKP + kk + 8];
            }
#pragma unroll
            for (int mf = 0; mf < 4; mf++) {
                const int r0 = mf * 16 * BKP;
                const int r8 = r0 + 8 * BKP;
                uint32_t ah0 = *(const uint32_t*)&pah[r0 + kk];
                uint32_t ah1 = *(const uint32_t*)&pah[r8 + kk];
                uint32_t ah2 = *(const uint32_t*)&pah[r0 + kk + 8];
                uint32_t ah3 = *(const uint32_t*)&pah[r8 + kk + 8];
                uint32_t al0 = *(const uint32_t*)&pal[r0 + kk];
                uint32_t al1 = *(const uint32_t*)&pal[r8 + kk];
                uint32_t al2 = *(const uint32_t*)&pal[r0 + kk + 8];
                uint32_t al3 = *(const uint32_t*)&pal[r8 + kk + 8];
#pragma unroll
                for (int nf = 0; nf < 4; nf++) {
                    mma_bf16(acc[mf][nf], ah0, ah1, ah2, ah3, bh[nf][0], bh[nf][1]);
                    mma_bf16(acc[mf][nf], ah0, ah1, ah2, ah3, bl[nf][0], bl[nf][1]);
                    mma_bf16(acc[mf][nf], al0, al1, al2, al3, bh[nf][0], bh[nf][1]);
                }
            }
        }

        if (it + 1 < NIT) {
            __syncthreads();
            STORE_TILES(buf ^ 1);
            __syncthreads();
        }
    }

#pragma unroll
    for (int mf = 0; mf < 4; mf++) {
        int r0 = m0 + wm * 64 + mf * 16 + g;
#pragma unroll
        for (int nf = 0; nf < 4; nf++) {
            int col = n0 + wn * 32 + nf * 8 + tg * 2;
            float b0 = 0.f, b1 = 0.f;
            if (bias) { b0 = __ldg(&bias[col]); b1 = __ldg(&bias[col + 1]); }
            float2 o0 = { acc[mf][nf][0] + b0, acc[mf][nf][1] + b1 };
            float2 o1 = { acc[mf][nf][2] + b0, acc[mf][nf][3] + b1 };
            *(float2*)&C[(size_t)r0 * N + col]       = o0;
            *(float2*)&C[(size_t)(r0 + 8) * N + col] = o1;
        }
    }
#undef LOAD_TILES
#undef STORE_TILES
}

// ============================================================================
// Tensor-core flash attention (split-bf16), compacted keys.
// CTA = 128 queries x one (b,h). 4 warps, warp = 32 query rows.
// ============================================================================
#define AST 72   // padded bf16 row stride for K / V^T tiles

__global__ __launch_bounds__(128, 2)
void attn_tc_kernel(const float* __restrict__ Q,
                    const float* __restrict__ Kg_,
                    const float* __restrict__ Vg_,
                    const int*   __restrict__ idx,
                    const int*   __restrict__ nvp,
                    float* __restrict__ ys)
{
    __shared__ __nv_bfloat16 kh[64 * AST], kl[64 * AST];
    __shared__ __nv_bfloat16 vh[64 * AST], vl[64 * AST];

    const int tid  = threadIdx.x;
    const int lane = tid & 31;
    const int w    = tid >> 5;
    const int g    = lane >> 2;
    const int tg   = lane & 3;
    const int b    = blockIdx.z;
    const int h    = blockIdx.y;
    const int q0   = blockIdx.x * 128;

    const int nvb    = nvp[b];
    const int ntiles = (nvb + 63) >> 6;

    // ---- Q fragments, register-resident, split hi/lo ----
    const float* Qb = Q + ((size_t)(b * TT + q0 + w * 32)) * KK + h * SS;
    uint32_t qh_[2][4][4], ql_[2][4][4];
#pragma unroll
    for (int m = 0; m < 2; m++) {
#pragma unroll
        for (int ks = 0; ks < 4; ks++) {
            int r0 = m * 16 + g, r1 = r0 + 8;
            int d0 = ks * 16 + 2 * tg;
            float2 f00 = *(const float2*)(Qb + (size_t)r0 * KK + d0);
            float2 f10 = *(const float2*)(Qb + (size_t)r1 * KK + d0);
            float2 f01 = *(const float2*)(Qb + (size_t)r0 * KK + d0 + 8);
            float2 f11 = *(const float2*)(Qb + (size_t)r1 * KK + d0 + 8);
            split2(f00, qh_[m][ks][0], ql_[m][ks][0]);
            split2(f10, qh_[m][ks][1], ql_[m][ks][1]);
            split2(f01, qh_[m][ks][2], ql_[m][ks][2]);
            split2(f11, qh_[m][ks][3], ql_[m][ks][3]);
        }
    }

    float o[2][8][4];
#pragma unroll
    for (int m = 0; m < 2; m++)
#pragma unroll
        for (int nt = 0; nt < 8; nt++)
#pragma unroll
            for (int c = 0; c < 4; c++) o[m][nt][c] = 0.f;
    float mr[2][2] = { {-1e30f, -1e30f}, {-1e30f, -1e30f} };
    float lr[2][2] = { {0.f, 0.f}, {0.f, 0.f} };

    const int*   idxb = idx + b * TT;
    const float* Kg = Kg_ + (size_t)b * TT * KK + h * SS;
    const float* Vg = Vg_ + (size_t)b * TT * KK + h * SS;

    const int ikey = tid >> 1;       // 0..63
    const int half = tid & 1;        // 0..1 (d-half)

    for (int kt = 0; kt < ntiles; kt++) {
        __syncthreads();
        // ---- gather K tile [key][d], split bf16 ----
        {
            int slot = kt * 64 + ikey;
            int r = (slot < nvb) ? idxb[slot] : 0;
            const float* kp = Kg + (size_t)r * KK + half * 32;
            int dst = ikey * AST + half * 32;
#pragma unroll
            for (int j = 0; j < 8; j++) {
                float4 f = *(const float4*)(kp + j * 4);
                uint32_t h0, l0, h1, l1;
                split2(make_float2(f.x, f.y), h0, l0);
                split2(make_float2(f.z, f.w), h1, l1);
                *(uint32_t*)&kh[dst + j * 4]     = h0;
                *(uint32_t*)&kh[dst + j * 4 + 2] = h1;
                *(uint32_t*)&kl[dst + j * 4]     = l0;
                *(uint32_t*)&kl[dst + j * 4 + 2] = l1;
            }
        }
        // ---- gather V tile, store transposed [d][key], split bf16 ----
        {
            int slot = kt * 64 + ikey;
            int r = (slot < nvb) ? idxb[slot] : 0;
            const float* vp = Vg + (size_t)r * KK + half * 32;
#pragma unroll
            for (int j = 0; j < 8; j++) {
                float4 f = *(const float4*)(vp + j * 4);
                int dd = half * 32 + j * 4;
                __nv_bfloat16 hh, ll;
                split_bf16(f.x, hh, ll); vh[(dd+0)*AST + ikey] = hh; vl[(dd+0)*AST + ikey] = ll;
                split_bf16(f.y, hh, ll); vh[(dd+1)*AST + ikey] = hh; vl[(dd+1)*AST + ikey] = ll;
                split_bf16(f.z, hh, ll); vh[(dd+2)*AST + ikey] = hh; vl[(dd+2)*AST + ikey] = ll;
                split_bf16(f.w, hh, ll); vh[(dd+3)*AST + ikey] = hh; vl[(dd+3)*AST + ikey] = ll;
            }
        }
        __syncthreads();

        // ---- S = Q K^T (split-bf16, 3 MMAs per fragment) ----
        float s[2][8][4];
#pragma unroll
        for (int m = 0; m < 2; m++)
#pragma unroll
            for (int nt = 0; nt < 8; nt++)
#pragma unroll
                for (int c = 0; c < 4; c++) s[m][nt][c] = 0.f;

#pragma unroll
        for (int ks = 0; ks < 4; ks++) {
            const int kk = ks * 16 + 2 * tg;
#pragma unroll
            for (int nt = 0; nt < 8; nt++) {
                const int rr = (nt * 8 + g) * AST + kk;
                uint32_t bh0 = *(const uint32_t*)&kh[rr];
                uint32_t bh1 = *(const uint32_t*)&kh[rr + 8];
                uint32_t bl0 = *(const uint32_t*)&kl[rr];
                uint32_t bl1 = *(const uint32_t*)&kl[rr + 8];
#pragma unroll
                for (int m = 0; m < 2; m++) {
                    mma_bf16(s[m][nt], qh_[m][ks][0], qh_[m][ks][1], qh_[m][ks][2], qh_[m][ks][3], bh0, bh1);
                    mma_bf16(s[m][nt], qh_[m][ks][0], qh_[m][ks][1], qh_[m][ks][2], qh_[m][ks][3], bl0, bl1);
                    mma_bf16(s[m][nt], ql_[m][ks][0], ql_[m][ks][1], ql_[m][ks][2], ql_[m][ks][3], bh0, bh1);
                }
            }
        }

        // ---- tail masking ----
        if (kt * 64 + 64 > nvb) {
#pragma unroll
            for (int nt = 0; nt < 8; nt++) {
                int c0 = kt * 64 + nt * 8 + 2 * tg;
                if (c0 >= nvb) {
                    s[0][nt][0] = s[0][nt][2] = -1e30f;
                    s[1][nt][0] = s[1][nt][2] = -1e30f;
                }
                if (c0 + 1 >= nvb) {
                    s[0][nt][1] = s[0][nt][3] = -1e30f;
                    s[1][nt][1] = s[1][nt][3] = -1e30f;
                }
            }
        }

        // ---- online softmax (per m-tile, per row-half) ----
#pragma unroll
        for (int m = 0; m < 2; m++) {
#pragma unroll
            for (int r = 0; r < 2; r++) {
                const int c0 = r * 2;
                float tmax = -1e30f;
#pragma unroll
                for (int nt = 0; nt < 8; nt++) {
                    tmax = fmaxf(tmax, s[m][nt][c0]);
                    tmax = fmaxf(tmax, s[m][nt][c0 + 1]);
                }
                tmax = fmaxf(tmax, __shfl_xor_sync(0xffffffffu, tmax, 1));
                tmax = fmaxf(tmax, __shfl_xor_sync(0xffffffffu, tmax, 2));
                float mn = fmaxf(mr[m][r], tmax);
                float sc = __expf(mr[m][r] - mn);
                mr[m][r] = mn;
                float ts = 0.f;
#pragma unroll
                for (int nt = 0; nt < 8; nt++) {
                    float p0 = __expf(s[m][nt][c0]     - mn);
                    float p1 = __expf(s[m][nt][c0 + 1] - mn);
                    s[m][nt][c0]     = p0;
                    s[m][nt][c0 + 1] = p1;
                    ts += p0 + p1;
                }
                ts += __shfl_xor_sync(0xffffffffu, ts, 1);
                ts += __shfl_xor_sync(0xffffffffu, ts, 2);
                lr[m][r] = lr[m][r] * sc + ts;
#pragma unroll
                for (int nt = 0; nt < 8; nt++) {
                    o[m][nt][c0]     *= sc;
                    o[m][nt][c0 + 1] *= sc;
                }
            }
        }

        // ---- O += P V (split-bf16) ----
#pragma unroll
        for (int ks = 0; ks < 4; ks++) {
            uint32_t ph[2][4], pl[2][4];
#pragma unroll
            for (int m = 0; m < 2; m++) {
                split2(make_float2(s[m][2*ks][0],   s[m][2*ks][1]),   ph[m][0], pl[m][0]);
                split2(make_float2(s[m][2*ks][2],   s[m][2*ks][3]),   ph[m][1], pl[m][1]);
                split2(make_float2(s[m][2*ks+1][0], s[m][2*ks+1][1]), ph[m][2], pl[m][2]);
                split2(make_float2(s[m][2*ks+1][2], s[m][2*ks+1][3]), ph[m][3], pl[m][3]);
            }
            const int kk = ks * 16 + 2 * tg;
#pragma unroll
            for (int nt = 0; nt < 8; nt++) {
                const int rr = (nt * 8 + g) * AST + kk;
                uint32_t vh0 = *(const uint32_t*)&vh[rr];
                uint32_t vh1 = *(const uint32_t*)&vh[rr + 8];
                uint32_t vl0 = *(const uint32_t*)&vl[rr];
                uint32_t vl1 = *(const uint32_t*)&vl[rr + 8];
#pragma unroll
                for (int m = 0; m < 2; m++) {
                    mma_bf16(o[m][nt], ph[m][0], ph[m][1], ph[m][2], ph[m][3], vh0, vh1);
                    mma_bf16(o[m][nt], ph[m][0], ph[m][1], ph[m][2], ph[m][3], vl0, vl1);
                    mma_bf16(o[m][nt], pl[m][0], pl[m][1], pl[m][2], pl[m][3], vh0, vh1);
                }
            }
        }
    }

    // ---- epilogue: normalize and store ----
#pragma unroll
    for (int m = 0; m < 2; m++) {
#pragma unroll
        for (int r = 0; r < 2; r++) {
            float inv = 1.f / lr[m][r];
            int row = q0 + w * 32 + m * 16 + g + r * 8;
            float* op = ys + ((size_t)(b * TT + row)) * KK + h * SS;
#pragma unroll
            for (int nt = 0; nt < 8; nt++) {
                float2 ov = { o[m][nt][r*2] * inv, o[m][nt][r*2 + 1] * inv };
                *(float2*)(op + nt * 8 + 2 * tg) = ov;
            }
        }
    }
}

// ============================================================================
// launch
// ============================================================================
extern "C" void kernel_launch(void* const* d_in, const int* in_sizes, int n_in,
                              void* d_out, int out_size)
{
    const float* x    = (const float*)d_in[0];
    const int*   mask = (const int*)  d_in[1];
    const float* Wk   = (const float*)d_in[2];
    const float* Wq   = (const float*)d_in[3];
    const float* Wv   = (const float*)d_in[4];
    const float* Wu   = (const float*)d_in[5];
    const float* bu   = (const float*)d_in[6];
    float* out = (float*)d_out;

    float *Q, *Kb, *V, *ys;
    int *idx, *nv;
    cudaGetSymbolAddress((void**)&Q,   g_Q);
    cudaGetSymbolAddress((void**)&Kb,  g_K);
    cudaGetSymbolAddress((void**)&V,   g_V);
    cudaGetSymbolAddress((void**)&ys,  g_ys);
    cudaGetSymbolAddress((void**)&idx, g_idx);
    cudaGetSymbolAddress((void**)&nv,  g_nv);

    cudaFuncSetAttribute(gemm_mma_kernel,
                         cudaFuncAttributeMaxDynamicSharedMemorySize, GEMM_SMEM);

    compact_kernel<<<BB, 1024>>>(mask, idx, nv);

    dim3 gg(KK / GBN, MROWS / GBM);   // (8, 32)
    gemm_mma_kernel<<<gg, 256, GEMM_SMEM>>>(x, Wq, nullptr, Q,  MROWS, KK);
    gemm_mma_kernel<<<gg, 256, GEMM_SMEM>>>(x, Wk, nullptr, Kb, MROWS, KK);
    gemm_mma_kernel<<<gg, 256, GEMM_SMEM>>>(x, Wv, nullptr, V,  MROWS, KK);

    dim3 ga(TT / 128, HH, BB);        // (16, 16, 2)
    attn_tc_kernel<<<ga, 128>>>(Q, Kb, V, idx, nv, ys);

    gemm_mma_kernel<<<gg, 256, GEMM_SMEM>>>(ys, Wu, bu, out, MROWS, KK);
}

// round 6
// speedup vs baseline: 3.1250x; 1.0118x over previous
#include <cuda_runtime.h>
#include <cuda_bf16.h>
#include <cstdint>

#define BB   2
#define TT   2048
#define KK   1024
#define HH   16
#define SS   64
#define MROWS (BB*TT)   // 4096

// ---- scratch: everything split bf16 hi/lo (no allocation allowed) ----
__device__ __nv_bfloat16 g_xh[MROWS*KK], g_xl[MROWS*KK];
__device__ __nv_bfloat16 g_Wqh[KK*KK],  g_Wql[KK*KK];
__device__ __nv_bfloat16 g_Wkh[KK*KK],  g_Wkl[KK*KK];
__device__ __nv_bfloat16 g_Wvh[KK*KK],  g_Wvl[KK*KK];
__device__ __nv_bfloat16 g_Wuh[KK*KK],  g_Wul[KK*KK];
__device__ __nv_bfloat16 g_Qh[MROWS*KK], g_Ql[MROWS*KK];
__device__ __nv_bfloat16 g_Kh[MROWS*KK], g_Kl[MROWS*KK];
__device__ __nv_bfloat16 g_Vh[MROWS*KK], g_Vl[MROWS*KK];
__device__ __nv_bfloat16 g_ysh[MROWS*KK], g_ysl[MROWS*KK];
__device__ int g_idx[BB*TT];
__device__ int g_nv [BB];

// ============================================================================
// helpers
// ============================================================================
__device__ __forceinline__ uint32_t smem_u32(const void* p) {
    uint32_t a;
    asm("{ .reg .u64 t; cvta.to.shared.u64 t, %1; cvt.u32.u64 %0, t; }"
        : "=r"(a) : "l"(p));
    return a;
}

__device__ __forceinline__ void mma_bf16(float d[4],
                                         uint32_t a0, uint32_t a1, uint32_t a2, uint32_t a3,
                                         uint32_t b0, uint32_t b1) {
    asm volatile(
        "mma.sync.aligned.m16n8k16.row.col.f32.bf16.bf16.f32 "
        "{%0,%1,%2,%3}, {%4,%5,%6,%7}, {%8,%9}, {%0,%1,%2,%3};"
        : "+f"(d[0]), "+f"(d[1]), "+f"(d[2]), "+f"(d[3])
        : "r"(a0), "r"(a1), "r"(a2), "r"(a3), "r"(b0), "r"(b1));
}

#define LDSM4(r0, r1, r2, r3, addr) \
    asm volatile("ldmatrix.sync.aligned.m8n8.x4.shared.b16 {%0,%1,%2,%3}, [%4];" \
                 : "=r"(r0), "=r"(r1), "=r"(r2), "=r"(r3) : "r"(addr))

__device__ __forceinline__ void split2(float2 f, uint32_t& h, uint32_t& l) {
    __nv_bfloat162 hh = __float22bfloat162_rn(f);
    float2 hf = __bfloat1622float2(hh);
    __nv_bfloat162 ll = __float22bfloat162_rn(make_float2(f.x - hf.x, f.y - hf.y));
    h = *(uint32_t*)&hh;
    l = *(uint32_t*)&ll;
}

// ============================================================================
// preprocessing: fp32 -> (hi, lo) bf16
// ============================================================================
__global__ __launch_bounds__(256)
void split_kernel(const float* __restrict__ in,
                  __nv_bfloat16* __restrict__ hi,
                  __nv_bfloat16* __restrict__ lo, int n2)
{
    for (int i = blockIdx.x * blockDim.x + threadIdx.x; i < n2;
         i += gridDim.x * blockDim.x) {
        float2 f = ((const float2*)in)[i];
        uint32_t h, l;
        split2(f, h, l);
        ((uint32_t*)hi)[i] = h;
        ((uint32_t*)lo)[i] = l;
    }
}

// ============================================================================
// mask compaction (unchanged, proven)
// ============================================================================
__global__ __launch_bounds__(1024)
void compact_kernel(const int* __restrict__ mask, int* __restrict__ idx,
                    int* __restrict__ nv)
{
    __shared__ int s[1024];
    const int b = blockIdx.x;
    const int t = threadIdx.x;
    const int m0 = mask[b * TT + 2 * t];
    const int m1 = mask[b * TT + 2 * t + 1];
    const int c  = m0 + m1;
    s[t] = c;
    __syncthreads();
    for (int off = 1; off < 1024; off <<= 1) {
        int v = s[t];
        int u = (t >= off) ? s[t - off] : 0;
        __syncthreads();
        s[t] = v + u;
        __syncthreads();
    }
    const int incl = s[t];
    const int excl = incl - c;
    if (m0) idx[b * TT + excl] = 2 * t;
    if (m1) idx[b * TT + excl + m0] = 2 * t + 1;
    if (t == 1023) nv[b] = incl;
}

// ============================================================================
// Split-bf16 GEMM v2: preprocessed bf16 hi/lo inputs, cp.async double buffer,
// ldmatrix fragment loads. C = A @ B^T. Output: split bf16 OR fp32(+bias).
// CTA 128x128, GBK=32, 8 warps (2m x 4n), 2 CTAs/SM.
// ============================================================================
#define GBK 32
#define NIT (KK / GBK)          // 32
#define BKP 40                  // padded bf16 row stride (80B: LDSM conflict-free)
#define ATILE (128 * BKP)       // 5120 bf16 per array-tile
#define GEMM_SMEM (8 * ATILE * 2)  // 2 bufs x 4 arrays = 81920 B

__global__ void __launch_bounds__(256, 2)
gemm_bf16_kernel(const __nv_bfloat16* __restrict__ Agh,
                 const __nv_bfloat16* __restrict__ Agl,
                 const __nv_bfloat16* __restrict__ Bgh,
                 const __nv_bfloat16* __restrict__ Bgl,
                 const float* __restrict__ bias,
                 float* __restrict__ Cf,
                 __nv_bfloat16* __restrict__ Ch,
                 __nv_bfloat16* __restrict__ Cl,
                 int M, int N)
{
    extern __shared__ __nv_bfloat16 sm[];
    const uint32_t sbase = smem_u32(sm);

    const int tid  = threadIdx.x;
    const int lane = tid & 31;
    const int wid  = tid >> 5;
    const int g    = lane >> 2;
    const int tg   = lane & 3;
    const int wm   = wid & 1;
    const int wn   = wid >> 1;
    const int m0   = blockIdx.y * 128;
    const int n0   = blockIdx.x * 128;

    const __nv_bfloat16* gsrc[4] = {
        Agh + (size_t)m0 * KK, Agl + (size_t)m0 * KK,
        Bgh + (size_t)n0 * KK, Bgl + (size_t)n0 * KK };

    // ldmatrix lane-base offsets (bf16 units)
    const uint32_t aoff = (uint32_t)((wm * 64 + (lane & 15)) * BKP + ((lane & 16) ? 8 : 0));
    const uint32_t boff = (uint32_t)((wn * 32 + (lane & 7) + ((lane & 16) ? 8 : 0)) * BKP
                                     + ((lane & 8) ? 8 : 0));

#define GISSUE(k0, bsel) do { \
    _Pragma("unroll") \
    for (int a = 0; a < 4; a++) { \
        uint32_t sd = sbase + (uint32_t)(((bsel) * 4 + a) * ATILE) * 2; \
        _Pragma("unroll") \
        for (int j = 0; j < 2; j++) { \
            int row = j * 64 + (tid >> 2); int cc = tid & 3; \
            uint32_t s = sd + (uint32_t)(row * BKP + cc * 8) * 2; \
            const __nv_bfloat16* gp = gsrc[a] + (size_t)row * KK + (k0) + cc * 8; \
            asm volatile("cp.async.cg.shared.global [%0], [%1], 16;" :: "r"(s), "l"(gp)); \
        } \
    } \
    asm volatile("cp.async.commit_group;"); \
} while (0)

    float acc[4][4][4];
#pragma unroll
    for (int i = 0; i < 4; i++)
#pragma unroll
        for (int j = 0; j < 4; j++)
#pragma unroll
            for (int r = 0; r < 4; r++) acc[i][j][r] = 0.f;

    GISSUE(0, 0);

    for (int it = 0; it < NIT; it++) {
        const int buf = it & 1;
        asm volatile("cp.async.wait_group 0;");
        __syncthreads();
        if (it + 1 < NIT) GISSUE((it + 1) * GBK, buf ^ 1);

        const uint32_t bb = sbase + (uint32_t)(buf * 4 * ATILE) * 2;
#pragma unroll
        for (int ks = 0; ks < 2; ks++) {
            const uint32_t ko = ks * 32;   // 16 bf16 * 2B
            uint32_t bh[4][2], bl[4][2];
            LDSM4(bh[0][0], bh[0][1], bh[1][0], bh[1][1],
                  bb + 2 * ATILE * 2 + boff * 2 + ko);
            LDSM4(bh[2][0], bh[2][1], bh[3][0], bh[3][1],
                  bb + 2 * ATILE * 2 + (boff + 16 * BKP) * 2 + ko);
            LDSM4(bl[0][0], bl[0][1], bl[1][0], bl[1][1],
                  bb + 3 * ATILE * 2 + boff * 2 + ko);
            LDSM4(bl[2][0], bl[2][1], bl[3][0], bl[3][1],
                  bb + 3 * ATILE * 2 + (boff + 16 * BKP) * 2 + ko);
#pragma unroll
            for (int mf = 0; mf < 4; mf++) {
                uint32_t ah0, ah1, ah2, ah3, al0, al1, al2, al3;
                LDSM4(ah0, ah1, ah2, ah3, bb + (aoff + mf * 16 * BKP) * 2 + ko);
                LDSM4(al0, al1, al2, al3, bb + ATILE * 2 + (aoff + mf * 16 * BKP) * 2 + ko);
#pragma unroll
                for (int nf = 0; nf < 4; nf++) {
                    mma_bf16(acc[mf][nf], ah0, ah1, ah2, ah3, bh[nf][0], bh[nf][1]);
                    mma_bf16(acc[mf][nf], ah0, ah1, ah2, ah3, bl[nf][0], bl[nf][1]);
                    mma_bf16(acc[mf][nf], al0, al1, al2, al3, bh[nf][0], bh[nf][1]);
                }
            }
        }
    }
#undef GISSUE

    // ---- epilogue ----
    if (Cf) {
#pragma unroll
        for (int mf = 0; mf < 4; mf++) {
            int r0 = m0 + wm * 64 + mf * 16 + g;
#pragma unroll
            for (int nf = 0; nf < 4; nf++) {
                int col = n0 + wn * 32 + nf * 8 + tg * 2;
                float b0 = 0.f, b1 = 0.f;
                if (bias) { b0 = __ldg(&bias[col]); b1 = __ldg(&bias[col + 1]); }
                float2 o0 = { acc[mf][nf][0] + b0, acc[mf][nf][1] + b1 };
                float2 o1 = { acc[mf][nf][2] + b0, acc[mf][nf][3] + b1 };
                *(float2*)&Cf[(size_t)r0 * N + col]       = o0;
                *(float2*)&Cf[(size_t)(r0 + 8) * N + col] = o1;
            }
        }
    } else {
#pragma unroll
        for (int mf = 0; mf < 4; mf++) {
            int r0 = m0 + wm * 64 + mf * 16 + g;
#pragma unroll
            for (int nf = 0; nf < 4; nf++) {
                int col = n0 + wn * 32 + nf * 8 + tg * 2;
                uint32_t h0, l0, h1, l1;
                split2(make_float2(acc[mf][nf][0], acc[mf][nf][1]), h0, l0);
                split2(make_float2(acc[mf][nf][2], acc[mf][nf][3]), h1, l1);
                *(uint32_t*)&Ch[(size_t)r0 * N + col]       = h0;
                *(uint32_t*)&Cl[(size_t)r0 * N + col]       = l0;
                *(uint32_t*)&Ch[(size_t)(r0 + 8) * N + col] = h1;
                *(uint32_t*)&Cl[(size_t)(r0 + 8) * N + col] = l1;
            }
        }
    }
}

// ============================================================================
// Tensor-core flash attention (split-bf16 inputs/outputs), compacted keys.
// CTA = 128 queries x one (b,h). 4 warps.
// ============================================================================
#define AST 72

__global__ __launch_bounds__(128, 2)
void attn_tc_kernel(const __nv_bfloat16* __restrict__ Qh_,
                    const __nv_bfloat16* __restrict__ Ql_,
                    const __nv_bfloat16* __restrict__ Kh_,
                    const __nv_bfloat16* __restrict__ Kl_,
                    const __nv_bfloat16* __restrict__ Vh_,
                    const __nv_bfloat16* __restrict__ Vl_,
                    const int* __restrict__ idx,
                    const int* __restrict__ nvp,
                    __nv_bfloat16* __restrict__ ysh,
                    __nv_bfloat16* __restrict__ ysl)
{
    __shared__ __nv_bfloat16 kh[64 * AST], kl[64 * AST];
    __shared__ __nv_bfloat16 vh[64 * AST], vl[64 * AST];

    const int tid  = threadIdx.x;
    const int lane = tid & 31;
    const int w    = tid >> 5;
    const int g    = lane >> 2;
    const int tg   = lane & 3;
    const int b    = blockIdx.z;
    const int h    = blockIdx.y;
    const int q0   = blockIdx.x * 128;

    const int nvb    = nvp[b];
    const int ntiles = (nvb + 63) >> 6;

    // ---- Q fragments straight from split-bf16 gmem ----
    const __nv_bfloat16* Qhb = Qh_ + (size_t)(b * TT + q0 + w * 32) * KK + h * SS;
    const __nv_bfloat16* Qlb = Ql_ + (size_t)(b * TT + q0 + w * 32) * KK + h * SS;
    uint32_t qh_[2][4][4], ql_[2][4][4];
#pragma unroll
    for (int m = 0; m < 2; m++) {
#pragma unroll
        for (int ks = 0; ks < 4; ks++) {
            int r0 = m * 16 + g, r1 = r0 + 8;
            int d0 = ks * 16 + 2 * tg;
            qh_[m][ks][0] = *(const uint32_t*)(Qhb + (size_t)r0 * KK + d0);
            qh_[m][ks][1] = *(const uint32_t*)(Qhb + (size_t)r1 * KK + d0);
            qh_[m][ks][2] = *(const uint32_t*)(Qhb + (size_t)r0 * KK + d0 + 8);
            qh_[m][ks][3] = *(const uint32_t*)(Qhb + (size_t)r1 * KK + d0 + 8);
            ql_[m][ks][0] = *(const uint32_t*)(Qlb + (size_t)r0 * KK + d0);
            ql_[m][ks][1] = *(const uint32_t*)(Qlb + (size_t)r1 * KK + d0);
            ql_[m][ks][2] = *(const uint32_t*)(Qlb + (size_t)r0 * KK + d0 + 8);
            ql_[m][ks][3] = *(const uint32_t*)(Qlb + (size_t)r1 * KK + d0 + 8);
        }
    }

    float o[2][8][4];
#pragma unroll
    for (int m = 0; m < 2; m++)
#pragma unroll
        for (int nt = 0; nt < 8; nt++)
#pragma unroll
            for (int c = 0; c < 4; c++) o[m][nt][c] = 0.f;
    float mr[2][2] = { {-1e30f, -1e30f}, {-1e30f, -1e30f} };
    float lr[2][2] = { {0.f, 0.f}, {0.f, 0.f} };

    const int* idxb = idx + b * TT;
    const __nv_bfloat16* Khb = Kh_ + (size_t)b * TT * KK + h * SS;
    const __nv_bfloat16* Klb = Kl_ + (size_t)b * TT * KK + h * SS;
    const __nv_bfloat16* Vhb = Vh_ + (size_t)b * TT * KK + h * SS;
    const __nv_bfloat16* Vlb = Vl_ + (size_t)b * TT * KK + h * SS;

    const int ikey = tid >> 1;       // 0..63
    const int half = tid & 1;        // d-half

    for (int kt = 0; kt < ntiles; kt++) {
        __syncthreads();
        int slot = kt * 64 + ikey;
        int r = (slot < nvb) ? idxb[slot] : 0;
        // ---- K tile: vectorized row copy (bf16) ----
        {
            const uint4* kph = (const uint4*)(Khb + (size_t)r * KK + half * 32);
            const uint4* kpl = (const uint4*)(Klb + (size_t)r * KK + half * 32);
            int dst = ikey * AST + half * 32;
#pragma unroll
            for (int j = 0; j < 4; j++) {
                *(uint4*)&kh[dst + j * 8] = kph[j];
                *(uint4*)&kl[dst + j * 8] = kpl[j];
            }
        }
        // ---- V tile: transposed scatter (bf16) ----
        {
            const __nv_bfloat162* vph = (const __nv_bfloat162*)(Vhb + (size_t)r * KK + half * 32);
            const __nv_bfloat162* vpl = (const __nv_bfloat162*)(Vlb + (size_t)r * KK + half * 32);
#pragma unroll
            for (int jj = 0; jj < 16; jj++) {
                int dd = half * 32 + 2 * jj;
                __nv_bfloat162 ph = vph[jj];
                __nv_bfloat162 pl = vpl[jj];
                vh[dd * AST + ikey]       = ph.x;
                vh[(dd + 1) * AST + ikey] = ph.y;
                vl[dd * AST + ikey]       = pl.x;
                vl[(dd + 1) * AST + ikey] = pl.y;
            }
        }
        __syncthreads();

        // ---- S = Q K^T ----
        float s[2][8][4];
#pragma unroll
        for (int m = 0; m < 2; m++)
#pragma unroll
            for (int nt = 0; nt < 8; nt++)
#pragma unroll
                for (int c = 0; c < 4; c++) s[m][nt][c] = 0.f;

#pragma unroll
        for (int ks = 0; ks < 4; ks++) {
            const int kk = ks * 16 + 2 * tg;
#pragma unroll
            for (int nt = 0; nt < 8; nt++) {
                const int rr = (nt * 8 + g) * AST + kk;
                uint32_t bh0 = *(const uint32_t*)&kh[rr];
                uint32_t bh1 = *(const uint32_t*)&kh[rr + 8];
                uint32_t bl0 = *(const uint32_t*)&kl[rr];
                uint32_t bl1 = *(const uint32_t*)&kl[rr + 8];
#pragma unroll
                for (int m = 0; m < 2; m++) {
                    mma_bf16(s[m][nt], qh_[m][ks][0], qh_[m][ks][1], qh_[m][ks][2], qh_[m][ks][3], bh0, bh1);
                    mma_bf16(s[m][nt], qh_[m][ks][0], qh_[m][ks][1], qh_[m][ks][2], qh_[m][ks][3], bl0, bl1);
                    mma_bf16(s[m][nt], ql_[m][ks][0], ql_[m][ks][1], ql_[m][ks][2], ql_[m][ks][3], bh0, bh1);
                }
            }
        }

        // ---- tail masking ----
        if (kt * 64 + 64 > nvb) {
#pragma unroll
            for (int nt = 0; nt < 8; nt++) {
                int c0 = kt * 64 + nt * 8 + 2 * tg;
                if (c0 >= nvb) {
                    s[0][nt][0] = s[0][nt][2] = -1e30f;
                    s[1][nt][0] = s[1][nt][2] = -1e30f;
                }
                if (c0 + 1 >= nvb) {
                    s[0][nt][1] = s[0][nt][3] = -1e30f;
                    s[1][nt][1] = s[1][nt][3] = -1e30f;
                }
            }
        }

        // ---- online softmax ----
#pragma unroll
        for (int m = 0; m < 2; m++) {
#pragma unroll
            for (int r2 = 0; r2 < 2; r2++) {
                const int c0 = r2 * 2;
                float tmax = -1e30f;
#pragma unroll
                for (int nt = 0; nt < 8; nt++) {
                    tmax = fmaxf(tmax, s[m][nt][c0]);
                    tmax = fmaxf(tmax, s[m][nt][c0 + 1]);
                }
                tmax = fmaxf(tmax, __shfl_xor_sync(0xffffffffu, tmax, 1));
                tmax = fmaxf(tmax, __shfl_xor_sync(0xffffffffu, tmax, 2));
                float mn = fmaxf(mr[m][r2], tmax);
                float sc = __expf(mr[m][r2] - mn);
                mr[m][r2] = mn;
                float ts = 0.f;
#pragma unroll
                for (int nt = 0; nt < 8; nt++) {
                    float p0 = __expf(s[m][nt][c0]     - mn);
                    float p1 = __expf(s[m][nt][c0 + 1] - mn);
                    s[m][nt][c0]     = p0;
                    s[m][nt][c0 + 1] = p1;
                    ts += p0 + p1;
                }
                ts += __shfl_xor_sync(0xffffffffu, ts, 1);
                ts += __shfl_xor_sync(0xffffffffu, ts, 2);
                lr[m][r2] = lr[m][r2] * sc + ts;
#pragma unroll
                for (int nt = 0; nt < 8; nt++) {
                    o[m][nt][c0]     *= sc;
                    o[m][nt][c0 + 1] *= sc;
                }
            }
        }

        // ---- O += P V ----
#pragma unroll
        for (int ks = 0; ks < 4; ks++) {
            uint32_t ph[2][4], pl[2][4];
#pragma unroll
            for (int m = 0; m < 2; m++) {
                split2(make_float2(s[m][2*ks][0],   s[m][2*ks][1]),   ph[m][0], pl[m][0]);
                split2(make_float2(s[m][2*ks][2],   s[m][2*ks][3]),   ph[m][1], pl[m][1]);
                split2(make_float2(s[m][2*ks+1][0], s[m][2*ks+1][1]), ph[m][2], pl[m][2]);
                split2(make_float2(s[m][2*ks+1][2], s[m][2*ks+1][3]), ph[m][3], pl[m][3]);
            }
            const int kk = ks * 16 + 2 * tg;
#pragma unroll
            for (int nt = 0; nt < 8; nt++) {
                const int rr = (nt * 8 + g) * AST + kk;
                uint32_t vh0 = *(const uint32_t*)&vh[rr];
                uint32_t vh1 = *(const uint32_t*)&vh[rr + 8];
                uint32_t vl0 = *(const uint32_t*)&vl[rr];
                uint32_t vl1 = *(const uint32_t*)&vl[rr + 8];
#pragma unroll
                for (int m = 0; m < 2; m++) {
                    mma_bf16(o[m][nt], ph[m][0], ph[m][1], ph[m][2], ph[m][3], vh0, vh1);
                    mma_bf16(o[m][nt], ph[m][0], ph[m][1], ph[m][2], ph[m][3], vl0, vl1);
                    mma_bf16(o[m][nt], pl[m][0], pl[m][1], pl[m][2], pl[m][3], vh0, vh1);
                }
            }
        }
    }

    // ---- epilogue: normalize, split, store bf16 hi/lo ----
#pragma unroll
    for (int m = 0; m < 2; m++) {
#pragma unroll
        for (int r2 = 0; r2 < 2; r2++) {
            float inv = 1.f / lr[m][r2];
            int row = q0 + w * 32 + m * 16 + g + r2 * 8;
            size_t off = (size_t)(b * TT + row) * KK + h * SS;
#pragma unroll
            for (int nt = 0; nt < 8; nt++) {
                uint32_t hh, ll;
                split2(make_float2(o[m][nt][r2*2] * inv, o[m][nt][r2*2+1] * inv), hh, ll);
                *(uint32_t*)&ysh[off + nt * 8 + 2 * tg] = hh;
                *(uint32_t*)&ysl[off + nt * 8 + 2 * tg] = ll;
            }
        }
    }
}

// ============================================================================
// launch
// ============================================================================
extern "C" void kernel_launch(void* const* d_in, const int* in_sizes, int n_in,
                              void* d_out, int out_size)
{
    const float* x    = (const float*)d_in[0];
    const int*   mask = (const int*)  d_in[1];
    const float* Wk   = (const float*)d_in[2];
    const float* Wq   = (const float*)d_in[3];
    const float* Wv   = (const float*)d_in[4];
    const float* Wu   = (const float*)d_in[5];
    const float* bu   = (const float*)d_in[6];
    float* out = (float*)d_out;

    __nv_bfloat16 *xh, *xl, *Wqh, *Wql, *Wkh, *Wkl, *Wvh, *Wvl, *Wuh, *Wul;
    __nv_bfloat16 *Qh, *Ql, *Kh, *Kl, *Vh, *Vl, *ysh, *ysl;
    int *idx, *nv;
    cudaGetSymbolAddress((void**)&xh,  g_xh);  cudaGetSymbolAddress((void**)&xl,  g_xl);
    cudaGetSymbolAddress((void**)&Wqh, g_Wqh); cudaGetSymbolAddress((void**)&Wql, g_Wql);
    cudaGetSymbolAddress((void**)&Wkh, g_Wkh); cudaGetSymbolAddress((void**)&Wkl, g_Wkl);
    cudaGetSymbolAddress((void**)&Wvh, g_Wvh); cudaGetSymbolAddress((void**)&Wvl, g_Wvl);
    cudaGetSymbolAddress((void**)&Wuh, g_Wuh); cudaGetSymbolAddress((void**)&Wul, g_Wul);
    cudaGetSymbolAddress((void**)&Qh,  g_Qh);  cudaGetSymbolAddress((void**)&Ql,  g_Ql);
    cudaGetSymbolAddress((void**)&Kh,  g_Kh);  cudaGetSymbolAddress((void**)&Kl,  g_Kl);
    cudaGetSymbolAddress((void**)&Vh,  g_Vh);  cudaGetSymbolAddress((void**)&Vl,  g_Vl);
    cudaGetSymbolAddress((void**)&ysh, g_ysh); cudaGetSymbolAddress((void**)&ysl, g_ysl);
    cudaGetSymbolAddress((void**)&idx, g_idx); cudaGetSymbolAddress((void**)&nv,  g_nv);

    cudaFuncSetAttribute(gemm_bf16_kernel,
                         cudaFuncAttributeMaxDynamicSharedMemorySize, GEMM_SMEM);

    // preprocessing
    split_kernel<<<512, 256>>>(x,  xh,  xl,  MROWS * KK / 2);
    split_kernel<<<256, 256>>>(Wq, Wqh, Wql, KK * KK / 2);
    split_kernel<<<256, 256>>>(Wk, Wkh, Wkl, KK * KK / 2);
    split_kernel<<<256, 256>>>(Wv, Wvh, Wvl, KK * KK / 2);
    split_kernel<<<256, 256>>>(Wu, Wuh, Wul, KK * KK / 2);
    compact_kernel<<<BB, 1024>>>(mask, idx, nv);

    dim3 gg(KK / 128, MROWS / 128);   // (8, 32)
    gemm_bf16_kernel<<<gg, 256, GEMM_SMEM>>>(xh, xl, Wqh, Wql, nullptr,
                                             nullptr, Qh, Ql, MROWS, KK);
    gemm_bf16_kernel<<<gg, 256, GEMM_SMEM>>>(xh, xl, Wkh, Wkl, nullptr,
                                             nullptr, Kh, Kl, MROWS, KK);
    gemm_bf16_kernel<<<gg, 256, GEMM_SMEM>>>(xh, xl, Wvh, Wvl, nullptr,
                                             nullptr, Vh, Vl, MROWS, KK);

    dim3 ga(TT / 128, HH, BB);        // (16, 16, 2)
    attn_tc_kernel<<<ga, 128>>>(Qh, Ql, Kh, Kl, Vh, Vl, idx, nv, ysh, ysl);

    gemm_bf16_kernel<<<gg, 256, GEMM_SMEM>>>(ysh, ysl, Wuh, Wul, bu,
                                             out, nullptr, nullptr, MROWS, KK);
}